// round 16
// baseline (speedup 1.0000x reference)
#include <cuda_runtime.h>
#include <cuda_bf16.h>

// Fused SSIM, R11: R4 trunk geometry (384 CTAs, 256x128 strips, 4-slot row
// ring, 2-row stages, zero-recycling ring, ticket reduction) but 256 threads
// x 1 px/thread: register ring halves to 11 float4 = 44 regs -> ~90 regs
// -> 2 CTAs/SM = 16 warps/SM (vs 10) at unchanged instruction count.

#define IMG_W 512
#define IMG_H 512
#define PLANE_STRIDE (512*512)
#define NTHR 256
#define NBLOCKS 384          // 48 planes * 2 x-strips * 4 y-bands
#define NSTEPS 138
#define C1_CONST 0.0001f
#define C2_CONST 0.0009f

#define W0 0.00102838f
#define W1 0.00759876f
#define W2 0.03600077f
#define W3 0.10936080f
#define W4 0.21300555f
#define W5 0.26601174f

__device__ float    g_partial[NBLOCKS];
__device__ unsigned g_cnt = 0;

__device__ __forceinline__ float gwt(int k) {
    switch (k) {
        case 0: case 10: return W0;
        case 1: case 9:  return W1;
        case 2: case 8:  return W2;
        case 3: case 7:  return W3;
        case 4: case 6:  return W4;
        default:         return W5;
    }
}

__device__ __forceinline__ void f4fma(float4 &a, const float4 v, const float w) {
    a.x = fmaf(v.x, w, a.x);
    a.y = fmaf(v.y, w, a.y);
    a.z = fmaf(v.z, w, a.z);
    a.w = fmaf(v.w, w, a.w);
}

__global__ void __launch_bounds__(NTHR, 2)
ssim_kernel(const float* __restrict__ img1, const float* __restrict__ img2,
            float* __restrict__ out) {
    // 4-row ring; S[slot][i] holds input px (x0 - 5 + i), i in 0..265
    __shared__ float4 S[4][268];
    __shared__ float  wsum[8];
    __shared__ int    s_last;

    const int t  = threadIdx.x;
    const int b  = blockIdx.x;
    const int plane = b >> 3;             // 8 tiles per plane
    const int x0 = (b & 1) * 256;
    const int y0 = ((b >> 1) & 3) * 128;

    const float* p1 = img1 + (size_t)plane * PLANE_STRIDE;
    const float* p2 = img2 + (size_t)plane * PLANE_STRIDE;

    // vertical scatter ring for output column x0 + t
    float4 acc[11];
#pragma unroll
    for (int j = 0; j < 11; ++j) acc[j] = make_float4(0.f, 0.f, 0.f, 0.f);
    float lsum = 0.f;

    auto load_row = [&](int step) {
        const int slot = step & 3;
        const int r    = y0 - 5 + step;
        const bool rok = ((unsigned)r < (unsigned)IMG_H) && (step < NSTEPS);
        const float* q1 = p1 + (size_t)(rok ? r : 0) * IMG_W;
        const float* q2 = p2 + (size_t)(rok ? r : 0) * IMG_W;
        {
            const int  gx = x0 - 5 + t;
            const bool ok = rok && ((unsigned)gx < (unsigned)IMG_W);
            const float a = ok ? __ldg(q1 + gx) : 0.f;
            const float c = ok ? __ldg(q2 + gx) : 0.f;
            S[slot][t] = make_float4(a, c, a * c, fmaf(a, a, c * c));
        }
        if (t < 10) {                     // tail: i = 256..265 -> gx = x0+251..x0+260
            const int  gx = x0 + 251 + t;
            const bool ok = rok && (gx < IMG_W);
            const float a = ok ? __ldg(q1 + gx) : 0.f;
            const float c = ok ? __ldg(q2 + gx) : 0.f;
            S[slot][256 + t] = make_float4(a, c, a * c, fmaf(a, a, c * c));
        }
    };

    auto epi = [&](const float4 q) {   // q = (mu1, mu2, e12, e11+e22)
        const float m11 = q.x * q.x;
        const float m22 = q.y * q.y;
        const float m12 = q.x * q.y;
        const float num = (2.f * m12 + C1_CONST) * (2.f * (q.z - m12) + C2_CONST);
        const float den = (m11 + m22 + C1_CONST) * ((q.w - m11 - m22) + C2_CONST);
        lsum += __fdividef(num, den);
    };

#define PROC(SV, RR) {                                                         \
    const float4* rp = S[(SV) & 3];                                            \
    float4 h = make_float4(0.f, 0.f, 0.f, 0.f);                                \
    _Pragma("unroll")                                                          \
    for (int k = 0; k < 11; ++k) f4fma(h, rp[t + k], gwt(k));                  \
    _Pragma("unroll")                                                          \
    for (int j = 0; j < 11; ++j) {                                             \
        const int sl = ((RR) + j) % 11;                                        \
        f4fma(acc[sl], h, gwt(j));                                             \
    }                                                                          \
    if ((SV) >= 10) epi(acc[RR]);                                              \
    acc[RR] = make_float4(0.f, 0.f, 0.f, 0.f);                                 \
}

    load_row(0);
    load_row(1);

    int s = 0;
#pragma unroll 1
    for (int blk = 0; blk < 6; ++blk) {          // 6 * 22 = 132 rows
#pragma unroll
        for (int it = 0; it < 11; ++it) {
            __syncthreads();
            load_row(s + 2);
            load_row(s + 3);
            PROC(s,     (2 * it) % 11);
            PROC(s + 1, (2 * it + 1) % 11);
            s += 2;
        }
    }
#pragma unroll
    for (int it = 0; it < 3; ++it) {             // rows 132..137 (132 % 11 == 0)
        __syncthreads();
        load_row(s + 2);
        load_row(s + 3);
        PROC(s,     2 * it);
        PROC(s + 1, 2 * it + 1);
        s += 2;
    }
#undef PROC

    // deterministic per-CTA partial (8 warps)
    float v = lsum;
#pragma unroll
    for (int o = 16; o; o >>= 1) v += __shfl_xor_sync(0xffffffffu, v, o);
    if ((t & 31) == 0) wsum[t >> 5] = v;
    __syncthreads();
    if (t == 0) {
        g_partial[b] = ((wsum[0] + wsum[1]) + (wsum[2] + wsum[3])) +
                       ((wsum[4] + wsum[5]) + (wsum[6] + wsum[7]));
        __threadfence();
        const unsigned tk = atomicInc(&g_cnt, NBLOCKS - 1);  // self-resetting
        s_last = (tk == NBLOCKS - 1);
    }
    __syncthreads();

    // last CTA: deterministic final reduction over 384 partials
    if (s_last) {
        float sv = __ldcg(&g_partial[t]) +
                   ((t < 128) ? __ldcg(&g_partial[t + 256]) : 0.f);
#pragma unroll
        for (int o = 16; o; o >>= 1) sv += __shfl_xor_sync(0xffffffffu, sv, o);
        if ((t & 31) == 0) wsum[t >> 5] = sv;
        __syncthreads();
        if (t == 0) {
            out[0] = (((wsum[0] + wsum[1]) + (wsum[2] + wsum[3])) +
                      ((wsum[4] + wsum[5]) + (wsum[6] + wsum[7]))) *
                     (1.0f / 12582912.0f);
        }
    }
}

extern "C" void kernel_launch(void* const* d_in, const int* in_sizes, int n_in,
                              void* d_out, int out_size) {
    const float* img1 = (const float*)d_in[0];
    const float* img2 = (const float*)d_in[1];
    (void)in_sizes; (void)n_in; (void)out_size;
    ssim_kernel<<<NBLOCKS, NTHR>>>(img1, img2, (float*)d_out);
}

// round 17
// speedup vs baseline: 1.9043x; 1.9043x over previous
#include <cuda_runtime.h>
#include <cuda_bf16.h>
#include <cstdint>

// Fused SSIM, R12: R4 trunk (4 conv quantities (a,c,ac,a^2+c^2) in float4,
// even/odd deinterleaved smem rows, 2 px/thread, register vertical scatter
// ring, (128,3)) with the loader's LDG->STS replaced by cp.async (LDGSTS)
// raw staging + LDS-based derive pass. PROC is byte-identical to the
// 117.5us baseline. In-kernel ticket reduction.

#define IMG_W 512
#define IMG_H 512
#define PLANE_STRIDE (512*512)
#define BW 256
#define NTHR 128
#define NBLOCKS 384          // 48 planes * 2 x-strips * 4 y-bands
#define NSTEPS 138
#define C1_CONST 0.0001f
#define C2_CONST 0.0009f

#define W0 0.00102838f
#define W1 0.00759876f
#define W2 0.03600077f
#define W3 0.10936080f
#define W4 0.21300555f
#define W5 0.26601174f

__device__ float    g_partial[NBLOCKS];
__device__ unsigned g_cnt = 0;

__device__ __forceinline__ float gwt(int k) {
    switch (k) {
        case 0: case 10: return W0;
        case 1: case 9:  return W1;
        case 2: case 8:  return W2;
        case 3: case 7:  return W3;
        case 4: case 6:  return W4;
        default:         return W5;
    }
}

__device__ __forceinline__ void f4fma(float4 &a, const float4 v, const float w) {
    a.x = fmaf(v.x, w, a.x);
    a.y = fmaf(v.y, w, a.y);
    a.z = fmaf(v.z, w, a.z);
    a.w = fmaf(v.w, w, a.w);
}

__device__ __forceinline__ void cpasync16(uint32_t dst_smem, const void* src) {
    asm volatile("cp.async.cg.shared.global [%0], [%1], 16;"
                 :: "r"(dst_smem), "l"(src) : "memory");
}

__global__ void __launch_bounds__(NTHR, 3)
ssim_kernel(const float* __restrict__ img1, const float* __restrict__ img2,
            float* __restrict__ out) {
    // raw rows (8-slot ring): px p (rel) at index p+8; 272 px = chunks of 16B
    __shared__ __align__(16) float RawA[8][272];
    __shared__ __align__(16) float RawC[8][272];
    // derived float4 rows (4-slot ring), even/odd deinterleaved (as R4)
    __shared__ float4 Ev[4][136];
    __shared__ float4 Od[4][136];
    __shared__ float  wsum[4];
    __shared__ int    s_last;

    const int t  = threadIdx.x;
    const int b  = blockIdx.x;
    const int plane = b >> 3;
    const int x0 = (b & 1) * BW;
    const int y0 = ((b >> 1) & 3) * 128;

    const float* p1 = img1 + (size_t)plane * PLANE_STRIDE;
    const float* p2 = img2 + (size_t)plane * PLANE_STRIDE;

    const uint32_t rawA_u = (uint32_t)__cvta_generic_to_shared(&RawA[0][0]);
    const uint32_t rawC_u = (uint32_t)__cvta_generic_to_shared(&RawC[0][0]);

    float4 accA[11], accB[11];
#pragma unroll
    for (int j = 0; j < 11; ++j) {
        accA[j] = make_float4(0.f, 0.f, 0.f, 0.f);
        accB[j] = make_float4(0.f, 0.f, 0.f, 0.f);
    }
    float lsum = 0.f;

    // async fetch: raw row -> smem (no register dependence, no stall)
    auto fetch_row = [&](int step) {
        if (step >= NSTEPS) return;
        const int  slot = step & 7;
        const int  r    = y0 - 5 + step;
        const bool rok  = ((unsigned)r < (unsigned)IMG_H);
        if (t < 68) {
            const int  gx = x0 - 8 + 4 * t;                 // 16B-aligned chunk
            const bool ok = rok && ((unsigned)gx <= 508u);  // gx in [0,508]
            if (ok) {
                const uint32_t off = (uint32_t)slot * (272u * 4u) + (uint32_t)t * 16u;
                cpasync16(rawA_u + off, p1 + (size_t)r * IMG_W + gx);
                cpasync16(rawC_u + off, p2 + (size_t)r * IMG_W + gx);
            } else {
                const float4 z = make_float4(0.f, 0.f, 0.f, 0.f);
                *(float4*)&RawA[slot][4 * t] = z;
                *(float4*)&RawC[slot][4 * t] = z;
            }
        }
    };

    // derive: raw (a,c) -> float4 (a, c, ac, a^2+c^2), same layout as R4
    auto derive_row = [&](int step) {
        if (step >= NSTEPS) return;
        const int slot  = step & 7;
        const int fslot = step & 3;
        {
            const float2 A = *(const float2*)&RawA[slot][2 * t + 2];  // px 2t-6, 2t-5
            const float2 C = *(const float2*)&RawC[slot][2 * t + 2];
            Ev[fslot][t] = make_float4(A.x, C.x, A.x * C.x, fmaf(A.x, A.x, C.x * C.x));
            Od[fslot][t] = make_float4(A.y, C.y, A.y * C.y, fmaf(A.y, A.y, C.y * C.y));
        }
        if (t < 6) {                                        // px 250..261 (rel)
            const float2 A = *(const float2*)&RawA[slot][258 + 2 * t];
            const float2 C = *(const float2*)&RawC[slot][258 + 2 * t];
            Ev[fslot][128 + t] = make_float4(A.x, C.x, A.x * C.x, fmaf(A.x, A.x, C.x * C.x));
            Od[fslot][128 + t] = make_float4(A.y, C.y, A.y * C.y, fmaf(A.y, A.y, C.y * C.y));
        }
    };

    auto epi = [&](const float4 q) {   // q = (mu1, mu2, e12, e11+e22)
        const float m11 = q.x * q.x;
        const float m22 = q.y * q.y;
        const float m12 = q.x * q.y;
        const float num = (2.f * m12 + C1_CONST) * (2.f * (q.z - m12) + C2_CONST);
        const float den = (m11 + m22 + C1_CONST) * ((q.w - m11 - m22) + C2_CONST);
        lsum += __fdividef(num, den);
    };

#define PROC(SV, RR) {                                                         \
    const int sl_ = (SV) & 3;                                                  \
    const float4* ev = Ev[sl_];                                                \
    const float4* od = Od[sl_];                                                \
    float4 hA = make_float4(0.f, 0.f, 0.f, 0.f);                               \
    float4 hB = make_float4(0.f, 0.f, 0.f, 0.f);                               \
    float4 v_;                                                                 \
    v_ = od[t];     f4fma(hA, v_, W0);                                         \
    v_ = ev[t + 1]; f4fma(hA, v_, W1); f4fma(hB, v_, W0);                      \
    v_ = od[t + 1]; f4fma(hA, v_, W2); f4fma(hB, v_, W1);                      \
    v_ = ev[t + 2]; f4fma(hA, v_, W3); f4fma(hB, v_, W2);                      \
    v_ = od[t + 2]; f4fma(hA, v_, W4); f4fma(hB, v_, W3);                      \
    v_ = ev[t + 3]; f4fma(hA, v_, W5); f4fma(hB, v_, W4);                      \
    v_ = od[t + 3]; f4fma(hA, v_, W4); f4fma(hB, v_, W5);                      \
    v_ = ev[t + 4]; f4fma(hA, v_, W3); f4fma(hB, v_, W4);                      \
    v_ = od[t + 4]; f4fma(hA, v_, W2); f4fma(hB, v_, W3);                      \
    v_ = ev[t + 5]; f4fma(hA, v_, W1); f4fma(hB, v_, W2);                      \
    v_ = od[t + 5]; f4fma(hA, v_, W0); f4fma(hB, v_, W1);                      \
    v_ = ev[t + 6];                    f4fma(hB, v_, W0);                      \
    _Pragma("unroll")                                                          \
    for (int j = 0; j < 11; ++j) {                                             \
        const float w = gwt(j);                                                \
        const int sl = ((RR) + j) % 11;                                        \
        f4fma(accA[sl], hA, w);                                                \
        f4fma(accB[sl], hB, w);                                                \
    }                                                                          \
    if ((SV) >= 10) { epi(accA[RR]); epi(accB[RR]); }                          \
    accA[RR] = make_float4(0.f, 0.f, 0.f, 0.f);                                \
    accB[RR] = make_float4(0.f, 0.f, 0.f, 0.f);                                \
}

    // prologue: fetch rows 0..3 (two groups), derive rows 0,1
    fetch_row(0); fetch_row(1);
    asm volatile("cp.async.commit_group;" ::: "memory");
    fetch_row(2); fetch_row(3);
    asm volatile("cp.async.commit_group;" ::: "memory");
    asm volatile("cp.async.wait_group 1;" ::: "memory");   // rows 0,1 landed
    __syncthreads();
    derive_row(0); derive_row(1);

    int s = 0;
#pragma unroll 1
    for (int blk = 0; blk < 6; ++blk) {          // stages s=0..130
#pragma unroll
        for (int it = 0; it < 11; ++it) {
            fetch_row(s + 4); fetch_row(s + 5);
            asm volatile("cp.async.commit_group;" ::: "memory");
            asm volatile("cp.async.wait_group 1;" ::: "memory");  // s+2,s+3 landed
            __syncthreads();
            derive_row(s + 2); derive_row(s + 3);
            PROC(s,     (2 * it) % 11);
            PROC(s + 1, (2 * it + 1) % 11);
            s += 2;
        }
    }
#pragma unroll
    for (int it = 0; it < 3; ++it) {             // stages s=132,134,136
        fetch_row(s + 4); fetch_row(s + 5);
        asm volatile("cp.async.commit_group;" ::: "memory");
        asm volatile("cp.async.wait_group 1;" ::: "memory");
        __syncthreads();
        derive_row(s + 2); derive_row(s + 3);
        PROC(s,     2 * it);
        PROC(s + 1, 2 * it + 1);
        s += 2;
    }
#undef PROC
    asm volatile("cp.async.wait_group 0;" ::: "memory");   // drain

    // deterministic per-CTA partial (4 warps)
    float v = lsum;
#pragma unroll
    for (int o = 16; o; o >>= 1) v += __shfl_xor_sync(0xffffffffu, v, o);
    if ((t & 31) == 0) wsum[t >> 5] = v;
    __syncthreads();
    if (t == 0) {
        g_partial[b] = (wsum[0] + wsum[1]) + (wsum[2] + wsum[3]);
        __threadfence();
        const unsigned tk = atomicInc(&g_cnt, NBLOCKS - 1);  // self-resetting
        s_last = (tk == NBLOCKS - 1);
    }
    __syncthreads();

    // last CTA: deterministic final reduction over 384 partials
    if (s_last) {
        float sv = __ldcg(&g_partial[t]) + __ldcg(&g_partial[t + 128]) +
                   __ldcg(&g_partial[t + 256]);
#pragma unroll
        for (int o = 16; o; o >>= 1) sv += __shfl_xor_sync(0xffffffffu, sv, o);
        if ((t & 31) == 0) wsum[t >> 5] = sv;
        __syncthreads();
        if (t == 0) {
            out[0] = ((wsum[0] + wsum[1]) + (wsum[2] + wsum[3])) *
                     (1.0f / 12582912.0f);
        }
    }
}

extern "C" void kernel_launch(void* const* d_in, const int* in_sizes, int n_in,
                              void* d_out, int out_size) {
    const float* img1 = (const float*)d_in[0];
    const float* img2 = (const float*)d_in[1];
    (void)in_sizes; (void)n_in; (void)out_size;
    ssim_kernel<<<NBLOCKS, NTHR>>>(img1, img2, (float*)d_out);
}